// round 6
// baseline (speedup 1.0000x reference)
#include <cuda_runtime.h>
#include <cuda_fp16.h>
#include <cstdint>
#include <cfloat>

// ---------------- problem constants ----------------
#define BATCH     32
#define NSPATIAL  4096
#define CDIM      512
#define EDIM      128

#define TM        128                  // rows per CTA tile (M)
#define NCHUNK    (NSPATIAL / TM)      // 32 chunks per batch
#define KS        64                   // K per stage
#define NST       (CDIM / KS)          // 8 stages
#define NSLOT     3                    // pipeline depth
#define ASTR      72                   // padded row stride (fp16 elems) = 144B
#define TILEB     (TM * ASTR * 2)      // 18432 B per tile buffer
#define SMEM_DYN  (NSLOT * 3 * TILEB)  // 3 slots x (A, Bh, Bl) = 162KB

// scratch: per (batch, chunk, e): top3 + min3 (6 floats) -> 3 MB
__device__ float g_cand[BATCH * NCHUNK * EDIM * 6];
// pre-converted W^T in fp16 hi/lo, plain [E=128][C=512] K-major
__device__ __align__(16) __half g_Wh[EDIM * CDIM];
__device__ __align__(16) __half g_Wl[EDIM * CDIM];

// ---------------- helpers ----------------
__device__ __forceinline__ uint32_t smem_u32(const void* p) {
    uint32_t a;
    asm("{ .reg .u64 t; cvta.to.shared.u64 t, %1; cvt.u32.u64 %0, t; }"
        : "=r"(a) : "l"(p));
    return a;
}
__device__ __forceinline__ void ldx4(uint32_t* r, uint32_t addr) {
    asm volatile("ldmatrix.sync.aligned.m8n8.x4.shared.b16 {%0,%1,%2,%3}, [%4];"
                 : "=r"(r[0]), "=r"(r[1]), "=r"(r[2]), "=r"(r[3]) : "r"(addr));
}
__device__ __forceinline__ void mma_f16(float* c, const uint32_t* a,
                                        uint32_t b0, uint32_t b1) {
    asm volatile(
        "mma.sync.aligned.m16n8k16.row.col.f32.f16.f16.f32 "
        "{%0,%1,%2,%3}, {%4,%5,%6,%7}, {%8,%9}, {%0,%1,%2,%3};"
        : "+f"(c[0]), "+f"(c[1]), "+f"(c[2]), "+f"(c[3])
        : "r"(a[0]), "r"(a[1]), "r"(a[2]), "r"(a[3]), "r"(b0), "r"(b1));
}
__device__ __forceinline__ void cp16(uint32_t dst, const void* src) {
    asm volatile("cp.async.cg.shared.global [%0], [%1], 16;"
                 :: "r"(dst), "l"(src) : "memory");
}
#define CP_COMMIT() asm volatile("cp.async.commit_group;" ::: "memory")
#define CP_WAIT0()  asm volatile("cp.async.wait_group 0;" ::: "memory")

// ---- mbarrier ----
__device__ __forceinline__ void mbar_init(uint32_t a, uint32_t cnt) {
    asm volatile("mbarrier.init.shared.b64 [%0], %1;" :: "r"(a), "r"(cnt) : "memory");
}
__device__ __forceinline__ void mbar_arrive(uint32_t a) {
    asm volatile("mbarrier.arrive.shared.b64 _, [%0];" :: "r"(a) : "memory");
}
__device__ __forceinline__ void mbar_wait(uint32_t a, uint32_t parity) {
    uint32_t done;
    asm volatile(
        "{\n\t.reg .pred p;\n\t"
        "mbarrier.try_wait.parity.acquire.cta.shared::cta.b64 p, [%1], %2;\n\t"
        "selp.b32 %0, 1, 0, p;\n\t}"
        : "=r"(done) : "r"(a), "r"(parity) : "memory");
    if (!done) {
        asm volatile(
            "{\n\t.reg .pred P1;\n\t"
            "W%=:\n\t"
            "mbarrier.try_wait.parity.acquire.cta.shared::cta.b64 P1, [%0], %1, 0x989680;\n\t"
            "@P1 bra.uni D%=;\n\t"
            "bra.uni W%=;\n\t"
            "D%=:\n\t}"
            :: "r"(a), "r"(parity) : "memory");
    }
}

// fp32 pair -> fp16x2 (single rounding)
__device__ __forceinline__ uint32_t cvt_h2(float x, float y) {
    __half2 h = __floats2half2_rn(x, y);
    return *(uint32_t*)&h;
}
// fp32 pair -> fp16 hi + fp16 lo (residual)
__device__ __forceinline__ void cvt_hilo(float x, float y, uint32_t& h, uint32_t& l) {
    __half2 hh = __floats2half2_rn(x, y);
    float2 hf = __half22float2(hh);
    __half2 ll = __floats2half2_rn(x - hf.x, y - hf.y);
    h = *(uint32_t*)&hh;
    l = *(uint32_t*)&ll;
}

// ---- sorted top-3 / min-3 insertion ----
__device__ __forceinline__ void ins_top(float v, float& t0, float& t1, float& t2) {
    if (v > t2) { if (v > t1) { t2 = t1; if (v > t0) { t1 = t0; t0 = v; } else t1 = v; } else t2 = v; }
}
__device__ __forceinline__ void ins_min(float v, float& m0, float& m1, float& m2) {
    if (v < m2) { if (v < m1) { m2 = m1; if (v < m0) { m1 = m0; m0 = v; } else m1 = v; } else m2 = v; }
}

// ================= kernel 0: W^T -> fp16 hi/lo =================
__global__ void weldon_prepw_kernel(const float* __restrict__ W) {
    int idx = blockIdx.x * 512 + threadIdx.x;   // 0..32767
    int e = idx >> 8;                           // 0..127
    int k = (idx & 255) * 2;                    // 0..510 step 2
    float w0 = W[(size_t)k * EDIM + e];
    float w1 = W[(size_t)(k + 1) * EDIM + e];
    uint32_t h, l;
    cvt_hilo(w0, w1, h, l);
    *(uint32_t*)&g_Wh[(size_t)e * CDIM + k] = h;
    *(uint32_t*)&g_Wl[(size_t)e * CDIM + k] = l;
}

// ================= kernel 1: warp-specialized HMMA GEMM + pooling =================
// grid = (NCHUNK, BATCH), 512 threads:
//   warps 0-7  : consumers (64x32 warp tiles, wm = wid&1, wn = wid>>1)
//   warps 8-15 : producers (A: LDG+cvt+STS; B: cp.async)
__global__ __launch_bounds__(512, 1)
void weldon_gemm_pool_kernel(const float* __restrict__ x) {
    extern __shared__ char sm[];
    const uint32_t sb = smem_u32(sm);

    __shared__ float cand_s[2][EDIM][6];
    __shared__ __align__(8) unsigned long long s_full[NSLOT], s_empty[NSLOT];

    const int tid = threadIdx.x;
    const int lane = tid & 31;
    const int wid = tid >> 5;
    const int chunk = blockIdx.x;
    const int b = blockIdx.y;

    const float* xg = x + ((size_t)b * NSPATIAL + (size_t)chunk * TM) * CDIM;

    // slot byte offsets
    auto OFF_A  = [](int s) { return s * 3 * TILEB; };
    auto OFF_BH = [](int s) { return s * 3 * TILEB + TILEB; };
    auto OFF_BL = [](int s) { return s * 3 * TILEB + 2 * TILEB; };

    const uint32_t fullb  = smem_u32(&s_full[0]);
    const uint32_t emptyb = smem_u32(&s_empty[0]);

    if (tid == 0) {
#pragma unroll
        for (int i = 0; i < NSLOT; ++i) {
            mbar_init(fullb + i * 8, 256);    // 8 producer warps arrive
            mbar_init(emptyb + i * 8, 256);   // 8 consumer warps arrive
        }
    }
    __syncthreads();

    if (wid >= 8) {
        // ================= PRODUCER =================
        const int ptid = tid - 256;           // 0..255
        int slot = 0, pph = 1;                // fresh empty barriers pass at parity 1
#pragma unroll 2
        for (int s = 0; s < NST; ++s) {
            const int kb = s * KS;
            // A loads early (registers only -> no smem hazard before wait)
            float4 pf[8];
#pragma unroll
            for (int u = 0; u < 8; ++u) {
                int idx = ptid + u * 256;     // 0..2047 float4s
                int row = idx >> 4, kq = (idx & 15) * 4;
                pf[u] = *(const float4*)(xg + (size_t)row * CDIM + kb + kq);
            }
            mbar_wait(emptyb + slot * 8, pph);
            // B cp.async into slot
#pragma unroll
            for (int u = 0; u < 4; ++u) {
                int idx = ptid + u * 256;     // 0..1023 16B chunks
                int row = idx >> 3, ck = (idx & 7) * 8;
                int doff = row * (ASTR * 2) + ck * 2;
                cp16(sb + OFF_BH(slot) + doff,
                     (const char*)g_Wh + ((size_t)row * CDIM + kb + ck) * 2);
                cp16(sb + OFF_BL(slot) + doff,
                     (const char*)g_Wl + ((size_t)row * CDIM + kb + ck) * 2);
            }
            CP_COMMIT();
            // A convert + store
#pragma unroll
            for (int u = 0; u < 8; ++u) {
                int idx = ptid + u * 256;
                int row = idx >> 4, kq = (idx & 15) * 4;
                uint2 hv = make_uint2(cvt_h2(pf[u].x, pf[u].y), cvt_h2(pf[u].z, pf[u].w));
                *(uint2*)(sm + OFF_A(slot) + row * (ASTR * 2) + kq * 2) = hv;
            }
            CP_WAIT0();
            mbar_arrive(fullb + slot * 8);
            if (++slot == NSLOT) { slot = 0; pph ^= 1; }
        }
    } else {
        // ================= CONSUMER =================
        const int wm = wid & 1;               // 2 M-groups of 64
        const int wn = wid >> 1;              // 4 N-groups of 32

        int aoff[4], boff[2];
#pragma unroll
        for (int mt = 0; mt < 4; ++mt)
            aoff[mt] = ((wm * 64 + mt * 16 + (lane & 15)) * ASTR + (lane >> 4) * 8) * 2;
#pragma unroll
        for (int p = 0; p < 2; ++p)
            boff[p] = ((wn * 32 + p * 16 + (lane & 7) + (lane >> 4) * 8) * ASTR +
                       ((lane >> 3) & 1) * 8) * 2;

        float acc[4][4][4];
#pragma unroll
        for (int mt = 0; mt < 4; ++mt)
#pragma unroll
            for (int nt = 0; nt < 4; ++nt)
#pragma unroll
                for (int j = 0; j < 4; ++j) acc[mt][nt][j] = 0.f;

        int slot = 0, cph = 0;
#pragma unroll 2
        for (int s = 0; s < NST; ++s) {
            mbar_wait(fullb + slot * 8, cph);
#pragma unroll
            for (int k16 = 0; k16 < 4; ++k16) {
                const int kbyte = k16 * 32;
                uint32_t a_r[4][4], b_h[2][4], b_l[2][4];
#pragma unroll
                for (int mt = 0; mt < 4; ++mt)
                    ldx4(a_r[mt], sb + OFF_A(slot) + aoff[mt] + kbyte);
#pragma unroll
                for (int p = 0; p < 2; ++p) {
                    ldx4(b_h[p], sb + OFF_BH(slot) + boff[p] + kbyte);
                    ldx4(b_l[p], sb + OFF_BL(slot) + boff[p] + kbyte);
                }
#pragma unroll
                for (int mt = 0; mt < 4; ++mt)
#pragma unroll
                    for (int nt = 0; nt < 4; ++nt) {
                        uint32_t bh0 = b_h[nt >> 1][(nt & 1) * 2];
                        uint32_t bh1 = b_h[nt >> 1][(nt & 1) * 2 + 1];
                        uint32_t bl0 = b_l[nt >> 1][(nt & 1) * 2];
                        uint32_t bl1 = b_l[nt >> 1][(nt & 1) * 2 + 1];
                        mma_f16(acc[mt][nt], a_r[mt], bh0, bh1);
                        mma_f16(acc[mt][nt], a_r[mt], bl0, bl1);
                    }
            }
            mbar_arrive(emptyb + slot * 8);
            if (++slot == NSLOT) { slot = 0; cph ^= 1; }
        }

        // ---- epilogue: register-level per-column top3/min3 via shuffles ----
#pragma unroll
        for (int ci = 0; ci < 8; ++ci) {
            const int nt = ci >> 1, h = ci & 1;
            float t0 = -FLT_MAX, t1 = -FLT_MAX, t2 = -FLT_MAX;
            float m0 = FLT_MAX, m1 = FLT_MAX, m2 = FLT_MAX;
#pragma unroll
            for (int mt = 0; mt < 4; ++mt) {
                float v0 = acc[mt][nt][h];
                float v1 = acc[mt][nt][h + 2];
                ins_top(v0, t0, t1, t2); ins_min(v0, m0, m1, m2);
                ins_top(v1, t0, t1, t2); ins_min(v1, m0, m1, m2);
            }
#pragma unroll
            for (int msk = 4; msk <= 16; msk <<= 1) {
                float o0 = __shfl_xor_sync(0xffffffffu, t0, msk);
                float o1 = __shfl_xor_sync(0xffffffffu, t1, msk);
                float o2 = __shfl_xor_sync(0xffffffffu, t2, msk);
                ins_top(o0, t0, t1, t2); ins_top(o1, t0, t1, t2); ins_top(o2, t0, t1, t2);
                float p0 = __shfl_xor_sync(0xffffffffu, m0, msk);
                float p1 = __shfl_xor_sync(0xffffffffu, m1, msk);
                float p2 = __shfl_xor_sync(0xffffffffu, m2, msk);
                ins_min(p0, m0, m1, m2); ins_min(p1, m0, m1, m2); ins_min(p2, m0, m1, m2);
            }
            if (lane < 4) {
                int col = wn * 32 + nt * 8 + lane * 2 + h;
                cand_s[wm][col][0] = t0; cand_s[wm][col][1] = t1; cand_s[wm][col][2] = t2;
                cand_s[wm][col][3] = m0; cand_s[wm][col][4] = m1; cand_s[wm][col][5] = m2;
            }
        }
    }
    __syncthreads();

    if (tid < EDIM) {
        float t0 = cand_s[0][tid][0], t1 = cand_s[0][tid][1], t2 = cand_s[0][tid][2];
        float m0 = cand_s[0][tid][3], m1 = cand_s[0][tid][4], m2 = cand_s[0][tid][5];
        ins_top(cand_s[1][tid][0], t0, t1, t2);
        ins_top(cand_s[1][tid][1], t0, t1, t2);
        ins_top(cand_s[1][tid][2], t0, t1, t2);
        ins_min(cand_s[1][tid][3], m0, m1, m2);
        ins_min(cand_s[1][tid][4], m0, m1, m2);
        ins_min(cand_s[1][tid][5], m0, m1, m2);
        float* dst = g_cand + ((size_t)(b * NCHUNK + chunk) * EDIM + tid) * 6;
        dst[0] = t0; dst[1] = t1; dst[2] = t2;
        dst[3] = m0; dst[4] = m1; dst[5] = m2;
    }
}

// ================= kernel 2: merge + pool + L2 normalize =================
// grid = BATCH, block = (128, 8)
__global__ void weldon_reduce_kernel(float* __restrict__ out) {
    const int b = blockIdx.x;
    const int e = threadIdx.x;
    const int sub = threadIdx.y;

    __shared__ float cand_s[8][EDIM][6];
    __shared__ float ps_s[EDIM];
    __shared__ float wsum[4];

    float t0 = -FLT_MAX, t1 = -FLT_MAX, t2 = -FLT_MAX;
    float m0 = FLT_MAX, m1 = FLT_MAX, m2 = FLT_MAX;
    const float* bb = g_cand + (size_t)b * NCHUNK * EDIM * 6 + (size_t)e * 6;
#pragma unroll
    for (int c = sub; c < NCHUNK; c += 8) {
        const float* p = bb + (size_t)c * EDIM * 6;
        ins_top(p[0], t0, t1, t2);
        ins_top(p[1], t0, t1, t2);
        ins_top(p[2], t0, t1, t2);
        ins_min(p[3], m0, m1, m2);
        ins_min(p[4], m0, m1, m2);
        ins_min(p[5], m0, m1, m2);
    }
    cand_s[sub][e][0] = t0; cand_s[sub][e][1] = t1; cand_s[sub][e][2] = t2;
    cand_s[sub][e][3] = m0; cand_s[sub][e][4] = m1; cand_s[sub][e][5] = m2;
    __syncthreads();

    if (sub == 0) {
        for (int s2 = 1; s2 < 8; ++s2) {
            ins_top(cand_s[s2][e][0], t0, t1, t2);
            ins_top(cand_s[s2][e][1], t0, t1, t2);
            ins_top(cand_s[s2][e][2], t0, t1, t2);
            ins_min(cand_s[s2][e][3], m0, m1, m2);
            ins_min(cand_s[s2][e][4], m0, m1, m2);
            ins_min(cand_s[s2][e][5], m0, m1, m2);
        }
        float ps = (t0 + t1 + t2) + (m0 + m1 + m2);
        ps_s[e] = ps;
        float sq = ps * ps;
#pragma unroll
        for (int off = 16; off > 0; off >>= 1)
            sq += __shfl_xor_sync(0xffffffffu, sq, off);
        if ((e & 31) == 0) wsum[e >> 5] = sq;
    }
    __syncthreads();
    if (sub == 0) {
        float tot = wsum[0] + wsum[1] + wsum[2] + wsum[3];
        out[b * EDIM + e] = ps_s[e] * rsqrtf(fmaxf(tot, 1e-12f));
    }
}

extern "C" void kernel_launch(void* const* d_in, const int* in_sizes, int n_in,
                              void* d_out, int out_size) {
    const float* x = (const float*)d_in[0];   // [32, 64, 64, 512] fp32
    const float* W = (const float*)d_in[1];   // [512, 128] fp32
    float* out = (float*)d_out;               // [32, 128] fp32
    (void)in_sizes; (void)n_in; (void)out_size;

    cudaFuncSetAttribute(weldon_gemm_pool_kernel,
                         cudaFuncAttributeMaxDynamicSharedMemorySize, SMEM_DYN);

    weldon_prepw_kernel<<<64, 512>>>(W);
    weldon_gemm_pool_kernel<<<dim3(NCHUNK, BATCH), 512, SMEM_DYN>>>(x);
    weldon_reduce_kernel<<<BATCH, dim3(EDIM, 8)>>>(out);
}

// round 7
// speedup vs baseline: 1.4394x; 1.4394x over previous
#include <cuda_runtime.h>
#include <cuda_fp16.h>
#include <cstdint>
#include <cfloat>

// ---------------- problem constants ----------------
#define BATCH     32
#define NSPATIAL  4096
#define CDIM      512
#define EDIM      128

#define TM        128                  // rows per CTA tile (M)
#define NCHUNK    (NSPATIAL / TM)      // 32 chunks per batch
#define KS        64                   // K per stage
#define NST       (CDIM / KS)          // 8 stages
#define ASTR      72                   // padded row stride (fp16 elems) = 144B
#define TILEB     (TM * ASTR * 2)      // 18432 B per tile buffer
#define SMEM_DYN  (4 * TILEB)          // A0 A1 B0 B1 = 73.7KB

// scratch: per (batch, chunk, e): top3 + min3 (6 floats) -> 3 MB
__device__ float g_cand[BATCH * NCHUNK * EDIM * 6];
// pre-converted W^T in fp16, plain [E=128][C=512] K-major
__device__ __align__(16) __half g_Wh[EDIM * CDIM];

// ---------------- helpers ----------------
__device__ __forceinline__ uint32_t smem_u32(const void* p) {
    uint32_t a;
    asm("{ .reg .u64 t; cvta.to.shared.u64 t, %1; cvt.u32.u64 %0, t; }"
        : "=r"(a) : "l"(p));
    return a;
}
__device__ __forceinline__ void ldx4(uint32_t* r, uint32_t addr) {
    asm volatile("ldmatrix.sync.aligned.m8n8.x4.shared.b16 {%0,%1,%2,%3}, [%4];"
                 : "=r"(r[0]), "=r"(r[1]), "=r"(r[2]), "=r"(r[3]) : "r"(addr));
}
__device__ __forceinline__ void mma_f16(float* c, const uint32_t* a,
                                        uint32_t b0, uint32_t b1) {
    asm volatile(
        "mma.sync.aligned.m16n8k16.row.col.f32.f16.f16.f32 "
        "{%0,%1,%2,%3}, {%4,%5,%6,%7}, {%8,%9}, {%0,%1,%2,%3};"
        : "+f"(c[0]), "+f"(c[1]), "+f"(c[2]), "+f"(c[3])
        : "r"(a[0]), "r"(a[1]), "r"(a[2]), "r"(a[3]), "r"(b0), "r"(b1));
}
__device__ __forceinline__ void cp16(uint32_t dst, const void* src) {
    asm volatile("cp.async.cg.shared.global [%0], [%1], 16;"
                 :: "r"(dst), "l"(src) : "memory");
}
#define CP_COMMIT() asm volatile("cp.async.commit_group;" ::: "memory")
#define CP_WAIT0()  asm volatile("cp.async.wait_group 0;" ::: "memory")

// fp32 pair -> fp16x2 (single rounding)
__device__ __forceinline__ uint32_t cvt_h2(float x, float y) {
    __half2 h = __floats2half2_rn(x, y);
    return *(uint32_t*)&h;
}

// ---- sorted top-3 / min-3 insertion ----
__device__ __forceinline__ void ins_top(float v, float& t0, float& t1, float& t2) {
    if (v > t2) { if (v > t1) { t2 = t1; if (v > t0) { t1 = t0; t0 = v; } else t1 = v; } else t2 = v; }
}
__device__ __forceinline__ void ins_min(float v, float& m0, float& m1, float& m2) {
    if (v < m2) { if (v < m1) { m2 = m1; if (v < m0) { m1 = m0; m0 = v; } else m1 = v; } else m2 = v; }
}

// ================= kernel 0: W^T -> fp16 =================
__global__ void weldon_prepw_kernel(const float* __restrict__ W) {
    int idx = blockIdx.x * 512 + threadIdx.x;   // 0..32767
    int e = idx >> 8;                           // 0..127
    int k = (idx & 255) * 2;                    // 0..510 step 2
    float w0 = W[(size_t)k * EDIM + e];
    float w1 = W[(size_t)(k + 1) * EDIM + e];
    *(uint32_t*)&g_Wh[(size_t)e * CDIM + k] = cvt_h2(w0, w1);
}

// ================= kernel 1: HMMA GEMM + per-chunk pooling =================
// grid = (NCHUNK, BATCH), 512 threads (16 warps, 32x32 warp tiles)
__global__ __launch_bounds__(512, 1)
void weldon_gemm_pool_kernel(const float* __restrict__ x) {
    extern __shared__ char sm[];
    const uint32_t sb = smem_u32(sm);
    float* Fs = (float*)sm;                     // 64KB overlay after GEMM

    __shared__ float cand_s[4][EDIM][6];

    const int tid = threadIdx.x;
    const int lane = tid & 31;
    const int wid = tid >> 5;
    const int wm = wid & 3;                     // 4 M-groups of 32
    const int wn = wid >> 2;                    // 4 N-groups of 32
    const int chunk = blockIdx.x;
    const int b = blockIdx.y;

    const float* xg = x + ((size_t)b * NSPATIAL + (size_t)chunk * TM) * CDIM;

    // buffer byte offsets: A (2 bufs), B (2 bufs)
    auto OFF_A = [](int buf) { return buf * TILEB; };
    auto OFF_B = [](int buf) { return (2 + buf) * TILEB; };

    // ldmatrix per-lane address offsets (bytes within a tile)
    int aoff[2], boff[2];
#pragma unroll
    for (int mt = 0; mt < 2; ++mt)
        aoff[mt] = ((wm * 32 + mt * 16 + (lane & 15)) * ASTR + (lane >> 4) * 8) * 2;
#pragma unroll
    for (int p = 0; p < 2; ++p)
        boff[p] = ((wn * 32 + p * 16 + (lane & 7) + (lane >> 4) * 8) * ASTR +
                   ((lane >> 3) & 1) * 8) * 2;

    float acc[2][4][4];
#pragma unroll
    for (int mt = 0; mt < 2; ++mt)
#pragma unroll
        for (int nt = 0; nt < 4; ++nt)
#pragma unroll
            for (int j = 0; j < 4; ++j) acc[mt][nt][j] = 0.f;

    // ---- prologue: stage 0 ----
    {
#pragma unroll
        for (int u = 0; u < 4; ++u) {
            int idx = tid + u * 512;            // 0..2047 float4s
            int row = idx >> 4, kq = (idx & 15) * 4;
            float4 f = *(const float4*)(xg + (size_t)row * CDIM + kq);
            uint2 hv = make_uint2(cvt_h2(f.x, f.y), cvt_h2(f.z, f.w));
            *(uint2*)(sm + OFF_A(0) + row * (ASTR * 2) + kq * 2) = hv;
        }
#pragma unroll
        for (int u = 0; u < 2; ++u) {
            int idx = tid + u * 512;            // 0..1023 16B chunks
            int row = idx >> 3, ck = (idx & 7) * 8;
            int doff = row * (ASTR * 2) + ck * 2;
            cp16(sb + OFF_B(0) + doff, (const char*)g_Wh + ((size_t)row * CDIM + ck) * 2);
        }
        CP_COMMIT();
        CP_WAIT0();
        __syncthreads();
    }

    // ---- main stage loop ----
#pragma unroll
    for (int s = 0; s < NST; ++s) {
        const int buf = s & 1;
        const int nb = buf ^ 1;
        float4 pf[4];
        if (s + 1 < NST) {
            const int kb = (s + 1) * KS;
#pragma unroll
            for (int u = 0; u < 4; ++u) {
                int idx = tid + u * 512;
                int row = idx >> 4, kq = (idx & 15) * 4;
                pf[u] = *(const float4*)(xg + (size_t)row * CDIM + kb + kq);
            }
#pragma unroll
            for (int u = 0; u < 2; ++u) {
                int idx = tid + u * 512;
                int row = idx >> 3, ck = (idx & 7) * 8;
                int doff = row * (ASTR * 2) + ck * 2;
                cp16(sb + OFF_B(nb) + doff,
                     (const char*)g_Wh + ((size_t)row * CDIM + kb + ck) * 2);
            }
            CP_COMMIT();
        }

        // ---- MMA over current buffer: 4 k16 steps, 1 product ----
#pragma unroll
        for (int k16 = 0; k16 < 4; ++k16) {
            const int kbyte = k16 * 32;
            uint32_t a_r[2][4], b_r[2][4];
#pragma unroll
            for (int mt = 0; mt < 2; ++mt)
                ldx4(a_r[mt], sb + OFF_A(buf) + aoff[mt] + kbyte);
#pragma unroll
            for (int p = 0; p < 2; ++p)
                ldx4(b_r[p], sb + OFF_B(buf) + boff[p] + kbyte);
#pragma unroll
            for (int mt = 0; mt < 2; ++mt)
#pragma unroll
                for (int nt = 0; nt < 4; ++nt) {
                    uint32_t b0 = b_r[nt >> 1][(nt & 1) * 2];
                    uint32_t b1 = b_r[nt >> 1][(nt & 1) * 2 + 1];
                    mma_f16(acc[mt][nt], a_r[mt], b0, b1);
                }
        }

        if (s + 1 < NST) {
#pragma unroll
            for (int u = 0; u < 4; ++u) {
                int idx = tid + u * 512;
                int row = idx >> 4, kq = (idx & 15) * 4;
                uint2 hv = make_uint2(cvt_h2(pf[u].x, pf[u].y), cvt_h2(pf[u].z, pf[u].w));
                *(uint2*)(sm + OFF_A(nb) + row * (ASTR * 2) + kq * 2) = hv;
            }
            CP_WAIT0();
        }
        __syncthreads();
    }

    // ---- epilogue: acc -> Fs (overlay), then per-column pooling ----
    {
        const int gid = lane >> 2, tig = lane & 3;
#pragma unroll
        for (int mt = 0; mt < 2; ++mt)
#pragma unroll
            for (int nt = 0; nt < 4; ++nt) {
                int m0 = wm * 32 + mt * 16 + gid;
                int n0 = wn * 32 + nt * 8 + tig * 2;
                Fs[m0 * EDIM + n0] = acc[mt][nt][0];
                Fs[m0 * EDIM + n0 + 1] = acc[mt][nt][1];
                Fs[(m0 + 8) * EDIM + n0] = acc[mt][nt][2];
                Fs[(m0 + 8) * EDIM + n0 + 1] = acc[mt][nt][3];
            }
    }
    __syncthreads();

    {
        const int sub = tid >> 7;       // 0..3, each handles 32 rows
        const int e = tid & 127;
        float t0 = -FLT_MAX, t1 = -FLT_MAX, t2 = -FLT_MAX;
        float m0 = FLT_MAX, m1 = FLT_MAX, m2 = FLT_MAX;
#pragma unroll 4
        for (int r = sub * 32; r < sub * 32 + 32; ++r) {
            float v = Fs[r * EDIM + e];
            ins_top(v, t0, t1, t2);
            ins_min(v, m0, m1, m2);
        }
        cand_s[sub][e][0] = t0; cand_s[sub][e][1] = t1; cand_s[sub][e][2] = t2;
        cand_s[sub][e][3] = m0; cand_s[sub][e][4] = m1; cand_s[sub][e][5] = m2;
    }
    __syncthreads();

    if (tid < EDIM) {
        float t0 = -FLT_MAX, t1 = -FLT_MAX, t2 = -FLT_MAX;
        float m0 = FLT_MAX, m1 = FLT_MAX, m2 = FLT_MAX;
#pragma unroll
        for (int s2 = 0; s2 < 4; ++s2) {
            ins_top(cand_s[s2][tid][0], t0, t1, t2);
            ins_top(cand_s[s2][tid][1], t0, t1, t2);
            ins_top(cand_s[s2][tid][2], t0, t1, t2);
            ins_min(cand_s[s2][tid][3], m0, m1, m2);
            ins_min(cand_s[s2][tid][4], m0, m1, m2);
            ins_min(cand_s[s2][tid][5], m0, m1, m2);
        }
        float* dst = g_cand + ((size_t)(b * NCHUNK + chunk) * EDIM + tid) * 6;
        dst[0] = t0; dst[1] = t1; dst[2] = t2;
        dst[3] = m0; dst[4] = m1; dst[5] = m2;
    }
}

// ================= kernel 2: merge + pool + L2 normalize =================
// grid = BATCH, block = (128, 8)
__global__ void weldon_reduce_kernel(float* __restrict__ out) {
    const int b = blockIdx.x;
    const int e = threadIdx.x;
    const int sub = threadIdx.y;

    __shared__ float cand_s[8][EDIM][6];
    __shared__ float ps_s[EDIM];
    __shared__ float wsum[4];

    float t0 = -FLT_MAX, t1 = -FLT_MAX, t2 = -FLT_MAX;
    float m0 = FLT_MAX, m1 = FLT_MAX, m2 = FLT_MAX;
    const float* bb = g_cand + (size_t)b * NCHUNK * EDIM * 6 + (size_t)e * 6;
#pragma unroll
    for (int c = sub; c < NCHUNK; c += 8) {
        const float* p = bb + (size_t)c * EDIM * 6;
        ins_top(p[0], t0, t1, t2);
        ins_top(p[1], t0, t1, t2);
        ins_top(p[2], t0, t1, t2);
        ins_min(p[3], m0, m1, m2);
        ins_min(p[4], m0, m1, m2);
        ins_min(p[5], m0, m1, m2);
    }
    cand_s[sub][e][0] = t0; cand_s[sub][e][1] = t1; cand_s[sub][e][2] = t2;
    cand_s[sub][e][3] = m0; cand_s[sub][e][4] = m1; cand_s[sub][e][5] = m2;
    __syncthreads();

    if (sub == 0) {
        for (int s2 = 1; s2 < 8; ++s2) {
            ins_top(cand_s[s2][e][0], t0, t1, t2);
            ins_top(cand_s[s2][e][1], t0, t1, t2);
            ins_top(cand_s[s2][e][2], t0, t1, t2);
            ins_min(cand_s[s2][e][3], m0, m1, m2);
            ins_min(cand_s[s2][e][4], m0, m1, m2);
            ins_min(cand_s[s2][e][5], m0, m1, m2);
        }
        float ps = (t0 + t1 + t2) + (m0 + m1 + m2);
        ps_s[e] = ps;
        float sq = ps * ps;
#pragma unroll
        for (int off = 16; off > 0; off >>= 1)
            sq += __shfl_xor_sync(0xffffffffu, sq, off);
        if ((e & 31) == 0) wsum[e >> 5] = sq;
    }
    __syncthreads();
    if (sub == 0) {
        float tot = wsum[0] + wsum[1] + wsum[2] + wsum[3];
        out[b * EDIM + e] = ps_s[e] * rsqrtf(fmaxf(tot, 1e-12f));
    }
}

extern "C" void kernel_launch(void* const* d_in, const int* in_sizes, int n_in,
                              void* d_out, int out_size) {
    const float* x = (const float*)d_in[0];   // [32, 64, 64, 512] fp32
    const float* W = (const float*)d_in[1];   // [512, 128] fp32
    float* out = (float*)d_out;               // [32, 128] fp32
    (void)in_sizes; (void)n_in; (void)out_size;

    cudaFuncSetAttribute(weldon_gemm_pool_kernel,
                         cudaFuncAttributeMaxDynamicSharedMemorySize, SMEM_DYN);

    weldon_prepw_kernel<<<64, 512>>>(W);
    weldon_gemm_pool_kernel<<<dim3(NCHUNK, BATCH), 512, SMEM_DYN>>>(x);
    weldon_reduce_kernel<<<BATCH, dim3(EDIM, 8)>>>(out);
}

// round 8
// speedup vs baseline: 1.4524x; 1.0090x over previous
#include <cuda_runtime.h>
#include <cuda_fp16.h>
#include <cstdint>
#include <cfloat>

// ---------------- problem constants ----------------
#define BATCH     32
#define NSPATIAL  4096
#define CDIM      512
#define EDIM      128

#define TM        128                  // rows per CTA tile (M)
#define NCHUNK    (NSPATIAL / TM)      // 32 chunks per batch
#define KS        64                   // K per stage
#define NST       (CDIM / KS)          // 8 stages
#define ASTR      72                   // padded row stride (fp16 elems) = 144B
#define TILEB     (TM * ASTR * 2)      // 18432 B per tile buffer
#define SMEM_DYN  (6 * TILEB)          // A0..A2, B0..B2 = 110.6KB

// scratch: per (batch, chunk, e): top3 + min3 (6 floats) -> 3 MB
__device__ float g_cand[BATCH * NCHUNK * EDIM * 6];
// pre-converted W^T in fp16, plain [E=128][C=512] K-major
__device__ __align__(16) __half g_Wh[EDIM * CDIM];

// ---------------- helpers ----------------
__device__ __forceinline__ uint32_t smem_u32(const void* p) {
    uint32_t a;
    asm("{ .reg .u64 t; cvta.to.shared.u64 t, %1; cvt.u32.u64 %0, t; }"
        : "=r"(a) : "l"(p));
    return a;
}
__device__ __forceinline__ void ldx4(uint32_t* r, uint32_t addr) {
    asm volatile("ldmatrix.sync.aligned.m8n8.x4.shared.b16 {%0,%1,%2,%3}, [%4];"
                 : "=r"(r[0]), "=r"(r[1]), "=r"(r[2]), "=r"(r[3]) : "r"(addr));
}
__device__ __forceinline__ void mma_f16(float* c, const uint32_t* a,
                                        uint32_t b0, uint32_t b1) {
    asm volatile(
        "mma.sync.aligned.m16n8k16.row.col.f32.f16.f16.f32 "
        "{%0,%1,%2,%3}, {%4,%5,%6,%7}, {%8,%9}, {%0,%1,%2,%3};"
        : "+f"(c[0]), "+f"(c[1]), "+f"(c[2]), "+f"(c[3])
        : "r"(a[0]), "r"(a[1]), "r"(a[2]), "r"(a[3]), "r"(b0), "r"(b1));
}
__device__ __forceinline__ void cp16(uint32_t dst, const void* src) {
    asm volatile("cp.async.cg.shared.global [%0], [%1], 16;"
                 :: "r"(dst), "l"(src) : "memory");
}
#define CP_COMMIT() asm volatile("cp.async.commit_group;" ::: "memory")
#define CP_WAIT1()  asm volatile("cp.async.wait_group 1;" ::: "memory")

// fp32 pair -> fp16x2 (single rounding)
__device__ __forceinline__ uint32_t cvt_h2(float x, float y) {
    __half2 h = __floats2half2_rn(x, y);
    return *(uint32_t*)&h;
}

// ---- sorted top-3 / min-3 insertion ----
__device__ __forceinline__ void ins_top(float v, float& t0, float& t1, float& t2) {
    if (v > t2) { if (v > t1) { t2 = t1; if (v > t0) { t1 = t0; t0 = v; } else t1 = v; } else t2 = v; }
}
__device__ __forceinline__ void ins_min(float v, float& m0, float& m1, float& m2) {
    if (v < m2) { if (v < m1) { m2 = m1; if (v < m0) { m1 = m0; m0 = v; } else m1 = v; } else m2 = v; }
}

// ================= kernel 0: W^T -> fp16 =================
__global__ void weldon_prepw_kernel(const float* __restrict__ W) {
    int idx = blockIdx.x * 512 + threadIdx.x;   // 0..32767
    int e = idx >> 8;                           // 0..127
    int k = (idx & 255) * 2;                    // 0..510 step 2
    float w0 = W[(size_t)k * EDIM + e];
    float w1 = W[(size_t)(k + 1) * EDIM + e];
    *(uint32_t*)&g_Wh[(size_t)e * CDIM + k] = cvt_h2(w0, w1);
}

// ================= kernel 1: HMMA GEMM + per-chunk pooling =================
// grid = (NCHUNK, BATCH), 512 threads (16 warps, 32x32 warp tiles)
// 2-stage-deep prefetch: LDG(s+2) in regs, cvt(s+1)->smem, MMA(s); 3 smem bufs.
__global__ __launch_bounds__(512, 1)
void weldon_gemm_pool_kernel(const float* __restrict__ x) {
    extern __shared__ char sm[];
    const uint32_t sb = smem_u32(sm);
    float* Fs = (float*)sm;                     // 64KB overlay after GEMM

    __shared__ float cand_s[4][EDIM][6];

    const int tid = threadIdx.x;
    const int lane = tid & 31;
    const int wid = tid >> 5;
    const int wm = wid & 3;                     // 4 M-groups of 32
    const int wn = wid >> 2;                    // 4 N-groups of 32
    const int chunk = blockIdx.x;
    const int b = blockIdx.y;

    const float* xg = x + ((size_t)b * NSPATIAL + (size_t)chunk * TM) * CDIM;

    // buffer byte offsets: A (3 bufs), B (3 bufs)
    auto OFF_A = [](int buf) { return buf * TILEB; };
    auto OFF_B = [](int buf) { return (3 + buf) * TILEB; };

    // per-thread load indices (4 float4 of A, 2 x 16B of B per stage)
    const int arow = tid >> 2;                  // A rows: idx>>4 for idx=tid+u*512
    // ldmatrix per-lane address offsets (bytes within a tile)
    int aoff[2], boff[2];
#pragma unroll
    for (int mt = 0; mt < 2; ++mt)
        aoff[mt] = ((wm * 32 + mt * 16 + (lane & 15)) * ASTR + (lane >> 4) * 8) * 2;
#pragma unroll
    for (int p = 0; p < 2; ++p)
        boff[p] = ((wn * 32 + p * 16 + (lane & 7) + (lane >> 4) * 8) * ASTR +
                   ((lane >> 3) & 1) * 8) * 2;
    (void)arow;

    float acc[2][4][4];
#pragma unroll
    for (int mt = 0; mt < 2; ++mt)
#pragma unroll
        for (int nt = 0; nt < 4; ++nt)
#pragma unroll
            for (int j = 0; j < 4; ++j) acc[mt][nt][j] = 0.f;

    float4 pf[2][4];                            // 2-deep A register prefetch

    // ---- A load / convert helpers ----
    auto ldg_stage = [&](int s, float4* dst) {
        const int kb = s * KS;
#pragma unroll
        for (int u = 0; u < 4; ++u) {
            int idx = tid + u * 512;            // 0..2047 float4s
            int row = idx >> 4, kq = (idx & 15) * 4;
            dst[u] = *(const float4*)(xg + (size_t)row * CDIM + kb + kq);
        }
    };
    auto cvt_stage = [&](const float4* src, int buf) {
#pragma unroll
        for (int u = 0; u < 4; ++u) {
            int idx = tid + u * 512;
            int row = idx >> 4, kq = (idx & 15) * 4;
            uint2 hv = make_uint2(cvt_h2(src[u].x, src[u].y), cvt_h2(src[u].z, src[u].w));
            *(uint2*)(sm + OFF_A(buf) + row * (ASTR * 2) + kq * 2) = hv;
        }
    };
    auto cp_stage = [&](int s, int buf) {
        const int kb = s * KS;
#pragma unroll
        for (int u = 0; u < 2; ++u) {
            int idx = tid + u * 512;            // 0..1023 16B chunks
            int row = idx >> 3, ck = (idx & 7) * 8;
            int doff = row * (ASTR * 2) + ck * 2;
            cp16(sb + OFF_B(buf) + doff,
                 (const char*)g_Wh + ((size_t)row * CDIM + kb + ck) * 2);
        }
        CP_COMMIT();
    };

    // ---- prologue ----
    ldg_stage(0, pf[0]);
    ldg_stage(1, pf[1]);
    cp_stage(0, 0);
    cp_stage(1, 1);
    cvt_stage(pf[0], 0);

    // ---- main stage loop ----
#pragma unroll
    for (int s = 0; s < NST; ++s) {
        CP_WAIT1();                 // B(s) landed (own groups); B(s+1) may be in flight
        __syncthreads();            // publish B(s) + abuf[s%3]

        if (s + 2 < NST) {
            ldg_stage(s + 2, pf[s & 1]);        // pf[s&1] freed (stage s already cvt'd)
            cp_stage(s + 2, (s + 2) % 3);
        }
        if (s + 1 < NST)
            cvt_stage(pf[(s + 1) & 1], (s + 1) % 3);

        // ---- MMA on buffers s%3 ----
        const int ab = OFF_A(s % 3), bb = OFF_B(s % 3);
#pragma unroll
        for (int k16 = 0; k16 < 4; ++k16) {
            const int kbyte = k16 * 32;
            uint32_t a_r[2][4], b_r[2][4];
#pragma unroll
            for (int mt = 0; mt < 2; ++mt)
                ldx4(a_r[mt], sb + ab + aoff[mt] + kbyte);
#pragma unroll
            for (int p = 0; p < 2; ++p)
                ldx4(b_r[p], sb + bb + boff[p] + kbyte);
#pragma unroll
            for (int mt = 0; mt < 2; ++mt)
#pragma unroll
                for (int nt = 0; nt < 4; ++nt) {
                    uint32_t b0 = b_r[nt >> 1][(nt & 1) * 2];
                    uint32_t b1 = b_r[nt >> 1][(nt & 1) * 2 + 1];
                    mma_f16(acc[mt][nt], a_r[mt], b0, b1);
                }
        }
    }
    __syncthreads();

    // ---- epilogue: acc -> Fs (overlay), then per-column pooling ----
    {
        const int gid = lane >> 2, tig = lane & 3;
#pragma unroll
        for (int mt = 0; mt < 2; ++mt)
#pragma unroll
            for (int nt = 0; nt < 4; ++nt) {
                int m0 = wm * 32 + mt * 16 + gid;
                int n0 = wn * 32 + nt * 8 + tig * 2;
                Fs[m0 * EDIM + n0] = acc[mt][nt][0];
                Fs[m0 * EDIM + n0 + 1] = acc[mt][nt][1];
                Fs[(m0 + 8) * EDIM + n0] = acc[mt][nt][2];
                Fs[(m0 + 8) * EDIM + n0 + 1] = acc[mt][nt][3];
            }
    }
    __syncthreads();

    {
        const int sub = tid >> 7;       // 0..3, each handles 32 rows
        const int e = tid & 127;
        float t0 = -FLT_MAX, t1 = -FLT_MAX, t2 = -FLT_MAX;
        float m0 = FLT_MAX, m1 = FLT_MAX, m2 = FLT_MAX;
#pragma unroll 4
        for (int r = sub * 32; r < sub * 32 + 32; ++r) {
            float v = Fs[r * EDIM + e];
            ins_top(v, t0, t1, t2);
            ins_min(v, m0, m1, m2);
        }
        cand_s[sub][e][0] = t0; cand_s[sub][e][1] = t1; cand_s[sub][e][2] = t2;
        cand_s[sub][e][3] = m0; cand_s[sub][e][4] = m1; cand_s[sub][e][5] = m2;
    }
    __syncthreads();

    if (tid < EDIM) {
        float t0 = -FLT_MAX, t1 = -FLT_MAX, t2 = -FLT_MAX;
        float m0 = FLT_MAX, m1 = FLT_MAX, m2 = FLT_MAX;
#pragma unroll
        for (int s2 = 0; s2 < 4; ++s2) {
            ins_top(cand_s[s2][tid][0], t0, t1, t2);
            ins_top(cand_s[s2][tid][1], t0, t1, t2);
            ins_top(cand_s[s2][tid][2], t0, t1, t2);
            ins_min(cand_s[s2][tid][3], m0, m1, m2);
            ins_min(cand_s[s2][tid][4], m0, m1, m2);
            ins_min(cand_s[s2][tid][5], m0, m1, m2);
        }
        float* dst = g_cand + ((size_t)(b * NCHUNK + chunk) * EDIM + tid) * 6;
        dst[0] = t0; dst[1] = t1; dst[2] = t2;
        dst[3] = m0; dst[4] = m1; dst[5] = m2;
    }
}

// ================= kernel 2: merge + pool + L2 normalize =================
// grid = BATCH, block = (128, 8)
__global__ void weldon_reduce_kernel(float* __restrict__ out) {
    const int b = blockIdx.x;
    const int e = threadIdx.x;
    const int sub = threadIdx.y;

    __shared__ float cand_s[8][EDIM][6];
    __shared__ float ps_s[EDIM];
    __shared__ float wsum[4];

    float t0 = -FLT_MAX, t1 = -FLT_MAX, t2 = -FLT_MAX;
    float m0 = FLT_MAX, m1 = FLT_MAX, m2 = FLT_MAX;
    const float* bb = g_cand + (size_t)b * NCHUNK * EDIM * 6 + (size_t)e * 6;
#pragma unroll
    for (int c = sub; c < NCHUNK; c += 8) {
        const float* p = bb + (size_t)c * EDIM * 6;
        ins_top(p[0], t0, t1, t2);
        ins_top(p[1], t0, t1, t2);
        ins_top(p[2], t0, t1, t2);
        ins_min(p[3], m0, m1, m2);
        ins_min(p[4], m0, m1, m2);
        ins_min(p[5], m0, m1, m2);
    }
    cand_s[sub][e][0] = t0; cand_s[sub][e][1] = t1; cand_s[sub][e][2] = t2;
    cand_s[sub][e][3] = m0; cand_s[sub][e][4] = m1; cand_s[sub][e][5] = m2;
    __syncthreads();

    if (sub == 0) {
        for (int s2 = 1; s2 < 8; ++s2) {
            ins_top(cand_s[s2][e][0], t0, t1, t2);
            ins_top(cand_s[s2][e][1], t0, t1, t2);
            ins_top(cand_s[s2][e][2], t0, t1, t2);
            ins_min(cand_s[s2][e][3], m0, m1, m2);
            ins_min(cand_s[s2][e][4], m0, m1, m2);
            ins_min(cand_s[s2][e][5], m0, m1, m2);
        }
        float ps = (t0 + t1 + t2) + (m0 + m1 + m2);
        ps_s[e] = ps;
        float sq = ps * ps;
#pragma unroll
        for (int off = 16; off > 0; off >>= 1)
            sq += __shfl_xor_sync(0xffffffffu, sq, off);
        if ((e & 31) == 0) wsum[e >> 5] = sq;
    }
    __syncthreads();
    if (sub == 0) {
        float tot = wsum[0] + wsum[1] + wsum[2] + wsum[3];
        out[b * EDIM + e] = ps_s[e] * rsqrtf(fmaxf(tot, 1e-12f));
    }
}

extern "C" void kernel_launch(void* const* d_in, const int* in_sizes, int n_in,
                              void* d_out, int out_size) {
    const float* x = (const float*)d_in[0];   // [32, 64, 64, 512] fp32
    const float* W = (const float*)d_in[1];   // [512, 128] fp32
    float* out = (float*)d_out;               // [32, 128] fp32
    (void)in_sizes; (void)n_in; (void)out_size;

    cudaFuncSetAttribute(weldon_gemm_pool_kernel,
                         cudaFuncAttributeMaxDynamicSharedMemorySize, SMEM_DYN);

    weldon_prepw_kernel<<<64, 512>>>(W);
    weldon_gemm_pool_kernel<<<dim3(NCHUNK, BATCH), 512, SMEM_DYN>>>(x);
    weldon_reduce_kernel<<<BATCH, dim3(EDIM, 8)>>>(out);
}